// round 2
// baseline (speedup 1.0000x reference)
#include <cuda_runtime.h>

#define BLK 128
#define GRID 2048

// ---- smem layout (float offsets) ----
#define OFF_WSYM 0      // 10x32
#define OFF_BSYM 320    // 32
#define OFF_WIN  352    // 42x64
#define OFF_BIN  3040   // 64
#define OFF_W1   3104   // 64x64  (W2/B2, W3/B3 follow with stride 4160)
#define OFF_B1   7200   // 64
#define LAYER_STRIDE 4160
#define OFF_WR1  15584  // 64x32
#define OFF_BR1  17632  // 32
#define OFF_WR2  17664  // 32
#define OFF_WC1  17696  // 64x32
#define OFF_BC1  19744  // 32
#define OFF_WC2  19776  // 32x4
#define OFF_BC2  19904  // 4
#define SMEM_FLOATS 19908
#define SMEM_BYTES (SMEM_FLOATS * 4)

__device__ __forceinline__ float elu_f(float v) {
    if (v > 0.0f) return v;
    if (v < -0.03125f) return __expf(v) - 1.0f;
    // 4-term Taylor of expm1 for tiny |v| (rel err < 1e-8 in this range)
    return v * (1.0f + v * (0.5f + v * (0.16666667f + v * 0.041666668f)));
}

__device__ __forceinline__ void cp_smem(float* dst, const float* __restrict__ src, int n) {
    for (int i = threadIdx.x; i < n; i += BLK) dst[i] = src[i];
}

__global__ void __launch_bounds__(BLK) robustsym_kernel(
    const float* __restrict__ x,
    const float* __restrict__ gWsym, const float* __restrict__ gbsym,
    const float* __restrict__ gWin,  const float* __restrict__ gbin,
    const float* __restrict__ gW1,   const float* __restrict__ gb1,
    const float* __restrict__ gW2,   const float* __restrict__ gb2,
    const float* __restrict__ gW3,   const float* __restrict__ gb3,
    const float* __restrict__ gWr1,  const float* __restrict__ gbr1,
    const float* __restrict__ gWr2,  const float* __restrict__ gbr2,
    const float* __restrict__ gWc1,  const float* __restrict__ gbc1,
    const float* __restrict__ gWc2,  const float* __restrict__ gbc2,
    float* __restrict__ out, int B)
{
    extern __shared__ float S[];

    cp_smem(S + OFF_WSYM, gWsym, 320);
    cp_smem(S + OFF_BSYM, gbsym, 32);
    cp_smem(S + OFF_WIN,  gWin,  2688);
    cp_smem(S + OFF_BIN,  gbin,  64);
    cp_smem(S + OFF_W1,                  gW1, 4096);
    cp_smem(S + OFF_B1,                  gb1, 64);
    cp_smem(S + OFF_W1 + LAYER_STRIDE,   gW2, 4096);
    cp_smem(S + OFF_B1 + LAYER_STRIDE,   gb2, 64);
    cp_smem(S + OFF_W1 + 2*LAYER_STRIDE, gW3, 4096);
    cp_smem(S + OFF_B1 + 2*LAYER_STRIDE, gb3, 64);
    cp_smem(S + OFF_WR1, gWr1, 2048);
    cp_smem(S + OFF_BR1, gbr1, 32);
    cp_smem(S + OFF_WR2, gWr2, 32);
    cp_smem(S + OFF_WC1, gWc1, 2048);
    cp_smem(S + OFF_BC1, gbc1, 32);
    cp_smem(S + OFF_WC2, gWc2, 128);
    cp_smem(S + OFF_BC2, gbc2, 4);
    __syncthreads();

    const float br2v = gbr2[0];

    for (int row = blockIdx.x * BLK + threadIdx.x; row < B; row += gridDim.x * BLK) {
        // ---- load input row ----
        float xr[10];
        #pragma unroll
        for (int i = 0; i < 10; i++) xr[i] = x[(long long)row * 10 + i];

        const float am = xr[0], bod = xr[1], dox = xr[2], ph = xr[4], nit = xr[7];

        // ---- symbolic features (constants folded from reference formulas) ----
        float p_ph  = ph  < 6.5f   ? (6.5f   - ph ) * (1.0f/6.5f)  : (ph  > 8.5f ? (ph  - 8.5f) * (1.0f/8.5f) : 0.0f);
        float p_am  = am  < 0.001f ? (0.001f - am ) * 1000.0f      : (am  > 0.5f ? (am  - 0.5f) * 2.0f        : 0.0f);
        float p_bod = bod < 0.001f ? (0.001f - bod) * 1000.0f      : (bod > 5.0f ? (bod - 5.0f) * 0.2f        : 0.0f);
        float p_do  = dox < 6.0f   ? (6.0f   - dox) * (1.0f/6.0f)  : 0.0f;
        float p_nit = nit < 0.001f ? (0.001f - nit) * 1000.0f      : (nit > 10.0f ? (nit - 10.0f) * 0.1f      : 0.0f);

        float s_bact = am * 0.79999998f + bod * 0.099999998f - dox * 0.026666667f;
        float s_chem = ph * 0.088235293f + nit * 0.050000000f;
        float s_org  = bod * 0.13333333f - dox * 0.050000000f + am * 0.53333332f;
        float s_agr  = nit * 0.19999999980000002f;
        float psum   = p_ph + p_am + p_bod + p_do + p_nit;
        float resil  = 1.0f / (1.0f + psum + 1e-8f);

        float sym[10] = {p_ph, p_am, p_bod, p_do, p_nit, s_bact, s_chem, s_org, s_agr, resil};

        // ---- sym encoder: elu(sym @ W_sym + b_sym), 10 -> 32 ----
        float se[32];
        #pragma unroll
        for (int j = 0; j < 32; j++) se[j] = S[OFF_BSYM + j];
        #pragma unroll
        for (int k = 0; k < 10; k++) {
            float sk = sym[k];
            const float4* wr = (const float4*)(S + OFF_WSYM + k * 32);
            #pragma unroll
            for (int j = 0; j < 8; j++) {
                float4 w = wr[j];
                se[4*j+0] += sk * w.x; se[4*j+1] += sk * w.y;
                se[4*j+2] += sk * w.z; se[4*j+3] += sk * w.w;
            }
        }
        #pragma unroll
        for (int j = 0; j < 32; j++) se[j] = elu_f(se[j]);

        // ---- input proj: elu([x, se] @ W_in + b_in), 42 -> 64 ----
        float h[64];
        #pragma unroll
        for (int j = 0; j < 64; j++) h[j] = S[OFF_BIN + j];
        #pragma unroll
        for (int k = 0; k < 10; k++) {
            float hk = xr[k];
            const float4* wr = (const float4*)(S + OFF_WIN + k * 64);
            #pragma unroll
            for (int j = 0; j < 16; j++) {
                float4 w = wr[j];
                h[4*j+0] += hk * w.x; h[4*j+1] += hk * w.y;
                h[4*j+2] += hk * w.z; h[4*j+3] += hk * w.w;
            }
        }
        #pragma unroll 2
        for (int k = 0; k < 32; k++) {
            float hk = se[k];
            const float4* wr = (const float4*)(S + OFF_WIN + (10 + k) * 64);
            #pragma unroll
            for (int j = 0; j < 16; j++) {
                float4 w = wr[j];
                h[4*j+0] += hk * w.x; h[4*j+1] += hk * w.y;
                h[4*j+2] += hk * w.z; h[4*j+3] += hk * w.w;
            }
        }
        #pragma unroll
        for (int j = 0; j < 64; j++) h[j] = elu_f(h[j]);

        // ---- 3 residual blocks: h = h + elu(h @ W + b), 64 -> 64 ----
        #pragma unroll 1
        for (int l = 0; l < 3; l++) {
            const float* W = S + OFF_W1 + l * LAYER_STRIDE;
            const float* b = S + OFF_B1 + l * LAYER_STRIDE;
            float t[64];
            #pragma unroll
            for (int j = 0; j < 64; j++) t[j] = b[j];
            #pragma unroll 4
            for (int k = 0; k < 64; k++) {
                float hk = h[k];
                const float4* wr = (const float4*)(W + k * 64);
                #pragma unroll
                for (int j = 0; j < 16; j++) {
                    float4 w = wr[j];
                    t[4*j+0] += hk * w.x; t[4*j+1] += hk * w.y;
                    t[4*j+2] += hk * w.z; t[4*j+3] += hk * w.w;
                }
            }
            #pragma unroll
            for (int j = 0; j < 64; j++) h[j] += elu_f(t[j]);
        }

        // ---- regression head: elu(h @ W_r1 + b_r1) @ W_r2 + b_r2 ----
        float r[32];
        #pragma unroll
        for (int j = 0; j < 32; j++) r[j] = S[OFF_BR1 + j];
        #pragma unroll 4
        for (int k = 0; k < 64; k++) {
            float hk = h[k];
            const float4* wr = (const float4*)(S + OFF_WR1 + k * 32);
            #pragma unroll
            for (int j = 0; j < 8; j++) {
                float4 w = wr[j];
                r[4*j+0] += hk * w.x; r[4*j+1] += hk * w.y;
                r[4*j+2] += hk * w.z; r[4*j+3] += hk * w.w;
            }
        }
        float pred = br2v;
        #pragma unroll
        for (int j = 0; j < 32; j++) pred += elu_f(r[j]) * S[OFF_WR2 + j];

        // ---- classification head: elu(h @ W_c1 + b_c1) @ W_c2 + b_c2 ----
        float c[32];
        #pragma unroll
        for (int j = 0; j < 32; j++) c[j] = S[OFF_BC1 + j];
        #pragma unroll 4
        for (int k = 0; k < 64; k++) {
            float hk = h[k];
            const float4* wr = (const float4*)(S + OFF_WC1 + k * 32);
            #pragma unroll
            for (int j = 0; j < 8; j++) {
                float4 w = wr[j];
                c[4*j+0] += hk * w.x; c[4*j+1] += hk * w.y;
                c[4*j+2] += hk * w.z; c[4*j+3] += hk * w.w;
            }
        }
        float lg0 = S[OFF_BC2 + 0], lg1 = S[OFF_BC2 + 1];
        float lg2 = S[OFF_BC2 + 2], lg3 = S[OFF_BC2 + 3];
        #pragma unroll
        for (int j = 0; j < 32; j++) {
            float cj = elu_f(c[j]);
            const float4 w = ((const float4*)(S + OFF_WC2))[j];
            lg0 += cj * w.x; lg1 += cj * w.y; lg2 += cj * w.z; lg3 += cj * w.w;
        }

        // ---- store: out[0:B] = predictions, out[B:5B] = logits (row-major) ----
        out[row] = pred;
        float4 o; o.x = lg0; o.y = lg1; o.z = lg2; o.w = lg3;
        *reinterpret_cast<float4*>(out + B + 4LL * row) = o;
    }
}

extern "C" void kernel_launch(void* const* d_in, const int* in_sizes, int n_in,
                              void* d_out, int out_size) {
    const float* x    = (const float*)d_in[0];
    const float* Wsym = (const float*)d_in[1];
    const float* bsym = (const float*)d_in[2];
    const float* Win  = (const float*)d_in[3];
    const float* bin_ = (const float*)d_in[4];
    const float* W1   = (const float*)d_in[5];
    const float* b1   = (const float*)d_in[6];
    const float* W2   = (const float*)d_in[7];
    const float* b2   = (const float*)d_in[8];
    const float* W3   = (const float*)d_in[9];
    const float* b3   = (const float*)d_in[10];
    const float* Wr1  = (const float*)d_in[11];
    const float* br1  = (const float*)d_in[12];
    const float* Wr2  = (const float*)d_in[13];
    const float* br2  = (const float*)d_in[14];
    const float* Wc1  = (const float*)d_in[15];
    const float* bc1  = (const float*)d_in[16];
    const float* Wc2  = (const float*)d_in[17];
    const float* bc2  = (const float*)d_in[18];
    float* out = (float*)d_out;

    int B = in_sizes[0] / 10;

    cudaFuncSetAttribute(robustsym_kernel,
                         cudaFuncAttributeMaxDynamicSharedMemorySize, SMEM_BYTES);

    robustsym_kernel<<<GRID, BLK, SMEM_BYTES>>>(
        x, Wsym, bsym, Win, bin_, W1, b1, W2, b2, W3, b3,
        Wr1, br1, Wr2, br2, Wc1, bc1, Wc2, bc2, out, B);
}

// round 5
// speedup vs baseline: 1.6167x; 1.6167x over previous
#include <cuda_runtime.h>

#define THREADS 384
#define WARPS 12
#define GRID 148
#define SR 68               // staging row stride (floats): (68*r + c) % 32 = (4r+c)%32 -> conflict-free frags
#define TILE_ROWS 32

// ---- smem layout (float offsets) ----
// permuted weights: per GEMM, TK*TN*64 floats; element ((kt*TN+nt)*32+lane)*2+r =
//   W[kt*8 + lane%4 + 4r][nt*8 + lane/4]  (zero-padded)
#define OFF_WSYM 0                    // TK=2 TN=4 : 512
#define OFF_WIN  (OFF_WSYM + 512)     // TK=6 TN=8 : 3072
#define OFF_W1   (OFF_WIN + 3072)     // TK=8 TN=8 : 4096 x3
#define OFF_WR1  (OFF_W1 + 3*4096)    // TK=8 TN=4 : 2048
#define OFF_WC1  (OFF_WR1 + 2048)     // 2048
#define OFF_BSYM (OFF_WC1 + 2048)     // 32
#define OFF_BIN  (OFF_BSYM + 32)      // 64
#define OFF_B1   (OFF_BIN + 64)       // 64*3
#define OFF_BR1  (OFF_B1 + 192)       // 32
#define OFF_WR2  (OFF_BR1 + 32)       // 32
#define OFF_BC1  (OFF_WR2 + 32)       // 32
#define OFF_WC2  (OFF_BC1 + 32)       // 32x4 = 128
#define OFF_BC2  (OFF_WC2 + 128)      // 4
#define OFF_BR2  (OFF_BC2 + 4)        // 1 (+3 pad)
#define OFF_STAGE (OFF_BR2 + 4)
#define STAGE_PER_WARP (TILE_ROWS * SR)     // 2176
#define SMEM_FLOATS (OFF_STAGE + WARPS * STAGE_PER_WARP)
#define SMEM_BYTES  (SMEM_FLOATS * 4)

__device__ __forceinline__ float elu_f(float v) {
    if (v > 0.0f) return v;
    if (v < -0.03125f) return __expf(v) - 1.0f;
    return v * (1.0f + v * (0.5f + v * (0.16666667f + v * 0.041666668f)));
}

__device__ __forceinline__ unsigned tf32_hi(float v) {
    unsigned r;
    asm("cvt.rna.tf32.f32 %0, %1;" : "=r"(r) : "f"(v));
    return r;
}

__device__ __forceinline__ void mma_tf32(float* c, const unsigned* a, unsigned b0, unsigned b1) {
    asm volatile(
        "mma.sync.aligned.m16n8k8.row.col.f32.tf32.tf32.f32 "
        "{%0,%1,%2,%3},{%4,%5,%6,%7},{%8,%9},{%0,%1,%2,%3};\n"
        : "+f"(c[0]), "+f"(c[1]), "+f"(c[2]), "+f"(c[3])
        : "r"(a[0]), "r"(a[1]), "r"(a[2]), "r"(a[3]), "r"(b0), "r"(b1));
}

// Stage W[K,N] into permuted tf32-fragment layout with zero padding.
__device__ void stage_weights(float* dst, const float* __restrict__ src,
                              int K, int N, int TK, int TN) {
    int total = TK * TN * 64;
    for (int i = threadIdx.x; i < total; i += THREADS) {
        int r    = i & 1;
        int lane = (i >> 1) & 31;
        int t    = i >> 6;
        int kt = t / TN, nt = t % TN;
        int k = kt * 8 + (lane & 3) + r * 4;
        int n = nt * 8 + (lane >> 2);
        dst[i] = (k < K && n < N) ? src[k * N + n] : 0.0f;
    }
}

__device__ __forceinline__ void cp_smem(float* dst, const float* __restrict__ src, int n) {
    for (int i = threadIdx.x; i < n; i += THREADS) dst[i] = src[i];
}

// Warp GEMM: C[2][TN][4] += stage[:, colbase:colbase+8*TK] @ Wperm  (3xTF32)
template <int TK, int TN>
__device__ __forceinline__ void warp_gemm(float C[2][TN][4], const float* stage,
                                          int colbase, const float* Wp, int lane) {
    const int q = lane & 3, g = lane >> 2;
    #pragma unroll
    for (int kt = 0; kt < TK; kt++) {
        unsigned ah[2][4], al[2][4];
        #pragma unroll
        for (int mt = 0; mt < 2; mt++) {
            int r = mt * 16 + g;
            int c = colbase + kt * 8 + q;
            float a0 = stage[r * SR + c];
            float a1 = stage[(r + 8) * SR + c];
            float a2 = stage[r * SR + c + 4];
            float a3 = stage[(r + 8) * SR + c + 4];
            ah[mt][0] = tf32_hi(a0); al[mt][0] = __float_as_uint(a0 - __uint_as_float(ah[mt][0]));
            ah[mt][1] = tf32_hi(a1); al[mt][1] = __float_as_uint(a1 - __uint_as_float(ah[mt][1]));
            ah[mt][2] = tf32_hi(a2); al[mt][2] = __float_as_uint(a2 - __uint_as_float(ah[mt][2]));
            ah[mt][3] = tf32_hi(a3); al[mt][3] = __float_as_uint(a3 - __uint_as_float(ah[mt][3]));
        }
        #pragma unroll
        for (int nt = 0; nt < TN; nt++) {
            float2 w = *reinterpret_cast<const float2*>(Wp + ((kt * TN + nt) * 32 + lane) * 2);
            unsigned b0h = tf32_hi(w.x);
            unsigned b1h = tf32_hi(w.y);
            unsigned b0l = __float_as_uint(w.x - __uint_as_float(b0h));
            unsigned b1l = __float_as_uint(w.y - __uint_as_float(b1h));
            #pragma unroll
            for (int mt = 0; mt < 2; mt++) {
                mma_tf32(C[mt][nt], ah[mt], b0h, b1h);  // hi*hi
                mma_tf32(C[mt][nt], al[mt], b0h, b1h);  // lo*hi
                mma_tf32(C[mt][nt], ah[mt], b0l, b1l);  // hi*lo
            }
        }
    }
}

__global__ void __launch_bounds__(THREADS, 1) robustsym_mma_kernel(
    const float* __restrict__ x,
    const float* __restrict__ gWsym, const float* __restrict__ gbsym,
    const float* __restrict__ gWin,  const float* __restrict__ gbin,
    const float* __restrict__ gW1,   const float* __restrict__ gb1,
    const float* __restrict__ gW2,   const float* __restrict__ gb2,
    const float* __restrict__ gW3,   const float* __restrict__ gb3,
    const float* __restrict__ gWr1,  const float* __restrict__ gbr1,
    const float* __restrict__ gWr2,  const float* __restrict__ gbr2,
    const float* __restrict__ gWc1,  const float* __restrict__ gbc1,
    const float* __restrict__ gWc2,  const float* __restrict__ gbc2,
    float* __restrict__ out, int B)
{
    extern __shared__ float S[];

    // ---- one-time staging of all weights/biases ----
    stage_weights(S + OFF_WSYM, gWsym, 10, 32, 2, 4);
    stage_weights(S + OFF_WIN,  gWin,  42, 64, 6, 8);
    stage_weights(S + OFF_W1,            gW1, 64, 64, 8, 8);
    stage_weights(S + OFF_W1 + 4096,     gW2, 64, 64, 8, 8);
    stage_weights(S + OFF_W1 + 8192,     gW3, 64, 64, 8, 8);
    stage_weights(S + OFF_WR1, gWr1, 64, 32, 8, 4);
    stage_weights(S + OFF_WC1, gWc1, 64, 32, 8, 4);
    cp_smem(S + OFF_BSYM, gbsym, 32);
    cp_smem(S + OFF_BIN,  gbin,  64);
    cp_smem(S + OFF_B1,        gb1, 64);
    cp_smem(S + OFF_B1 + 64,   gb2, 64);
    cp_smem(S + OFF_B1 + 128,  gb3, 64);
    cp_smem(S + OFF_BR1, gbr1, 32);
    cp_smem(S + OFF_WR2, gWr2, 32);
    cp_smem(S + OFF_BC1, gbc1, 32);
    cp_smem(S + OFF_WC2, gWc2, 128);
    cp_smem(S + OFF_BC2, gbc2, 4);
    if (threadIdx.x == 0) S[OFF_BR2] = gbr2[0];
    __syncthreads();

    const int wid  = threadIdx.x >> 5;
    const int lane = threadIdx.x & 31;
    const int q = lane & 3, g = lane >> 2;
    float* stage = S + OFF_STAGE + wid * STAGE_PER_WARP;

    const int ntiles = (B + TILE_ROWS - 1) / TILE_ROWS;
    const int gw = blockIdx.x * WARPS + wid;

    for (int tile = gw; tile < ntiles; tile += GRID * WARPS) {
        const int row0 = tile * TILE_ROWS;

        // ---- phase 0: per-lane row load + symbolic features -> staging ----
        {
            int row = row0 + lane;
            int rq = row < B ? row : B - 1;
            float xr[10];
            #pragma unroll
            for (int i = 0; i < 10; i++) xr[i] = __ldg(x + (long long)rq * 10 + i);

            const float am = xr[0], bod = xr[1], dox = xr[2], ph = xr[4], nit = xr[7];
            float p_ph  = ph  < 6.5f   ? (6.5f   - ph ) * (1.0f/6.5f)  : (ph  > 8.5f ? (ph  - 8.5f) * (1.0f/8.5f) : 0.0f);
            float p_am  = am  < 0.001f ? (0.001f - am ) * 1000.0f      : (am  > 0.5f ? (am  - 0.5f) * 2.0f        : 0.0f);
            float p_bod = bod < 0.001f ? (0.001f - bod) * 1000.0f      : (bod > 5.0f ? (bod - 5.0f) * 0.2f        : 0.0f);
            float p_do  = dox < 6.0f   ? (6.0f   - dox) * (1.0f/6.0f)  : 0.0f;
            float p_nit = nit < 0.001f ? (0.001f - nit) * 1000.0f      : (nit > 10.0f ? (nit - 10.0f) * 0.1f      : 0.0f);
            float s_bact = am * 0.79999998f + bod * 0.099999998f - dox * 0.026666667f;
            float s_chem = ph * 0.088235293f + nit * 0.050000000f;
            float s_org  = bod * 0.13333333f - dox * 0.050000000f + am * 0.53333332f;
            float s_agr  = nit * 0.19999999980000002f;
            float psum   = p_ph + p_am + p_bod + p_do + p_nit;
            float resil  = 1.0f / (1.0f + psum + 1e-8f);

            float* sr = stage + lane * SR;
            #pragma unroll
            for (int i = 0; i < 10; i++) sr[i] = xr[i];
            sr[10] = p_ph; sr[11] = p_am; sr[12] = p_bod; sr[13] = p_do; sr[14] = p_nit;
            sr[15] = s_bact; sr[16] = s_chem; sr[17] = s_org; sr[18] = s_agr; sr[19] = resil;
            #pragma unroll
            for (int i = 20; i < 26; i++) sr[i] = 0.0f;   // pad for GEMM A (K 10->16)
            #pragma unroll
            for (int i = 42; i < 48; i++) sr[i] = 0.0f;   // pad for GEMM B (K 42->48)
        }
        __syncwarp();

        // ---- GEMM A: sym_enc = elu(sym @ W_sym + b_sym)  [K=16p, N=32] -> cols 10..41 ----
        {
            float C[2][4][4];
            #pragma unroll
            for (int mt = 0; mt < 2; mt++)
                #pragma unroll
                for (int nt = 0; nt < 4; nt++)
                    #pragma unroll
                    for (int i = 0; i < 4; i++) C[mt][nt][i] = 0.0f;
            warp_gemm<2, 4>(C, stage, 10, S + OFF_WSYM, lane);
            __syncwarp();
            #pragma unroll
            for (int mt = 0; mt < 2; mt++) {
                int r = mt * 16 + g;
                #pragma unroll
                for (int nt = 0; nt < 4; nt++) {
                    int col = nt * 8 + 2 * q;
                    float2 b = *reinterpret_cast<const float2*>(S + OFF_BSYM + col);
                    *reinterpret_cast<float2*>(stage + r * SR + 10 + col) =
                        make_float2(elu_f(C[mt][nt][0] + b.x), elu_f(C[mt][nt][1] + b.y));
                    *reinterpret_cast<float2*>(stage + (r + 8) * SR + 10 + col) =
                        make_float2(elu_f(C[mt][nt][2] + b.x), elu_f(C[mt][nt][3] + b.y));
                }
            }
        }
        __syncwarp();

        // ---- GEMM B: h = elu([x|sym_enc] @ W_in + b_in)  [K=48p, N=64] -> cols 0..63 ----
        {
            float C[2][8][4];
            #pragma unroll
            for (int mt = 0; mt < 2; mt++)
                #pragma unroll
                for (int nt = 0; nt < 8; nt++)
                    #pragma unroll
                    for (int i = 0; i < 4; i++) C[mt][nt][i] = 0.0f;
            warp_gemm<6, 8>(C, stage, 0, S + OFF_WIN, lane);
            __syncwarp();
            #pragma unroll
            for (int mt = 0; mt < 2; mt++) {
                int r = mt * 16 + g;
                #pragma unroll
                for (int nt = 0; nt < 8; nt++) {
                    int col = nt * 8 + 2 * q;
                    float2 b = *reinterpret_cast<const float2*>(S + OFF_BIN + col);
                    *reinterpret_cast<float2*>(stage + r * SR + col) =
                        make_float2(elu_f(C[mt][nt][0] + b.x), elu_f(C[mt][nt][1] + b.y));
                    *reinterpret_cast<float2*>(stage + (r + 8) * SR + col) =
                        make_float2(elu_f(C[mt][nt][2] + b.x), elu_f(C[mt][nt][3] + b.y));
                }
            }
        }
        __syncwarp();

        // ---- residual blocks: h = h + elu(h @ W + b)  x3 ----
        #pragma unroll 1
        for (int l = 0; l < 3; l++) {
            float C[2][8][4];
            #pragma unroll
            for (int mt = 0; mt < 2; mt++)
                #pragma unroll
                for (int nt = 0; nt < 8; nt++)
                    #pragma unroll
                    for (int i = 0; i < 4; i++) C[mt][nt][i] = 0.0f;
            warp_gemm<8, 8>(C, stage, 0, S + OFF_W1 + l * 4096, lane);
            __syncwarp();
            const float* bb = S + OFF_B1 + l * 64;
            #pragma unroll
            for (int mt = 0; mt < 2; mt++) {
                int r = mt * 16 + g;
                #pragma unroll
                for (int nt = 0; nt < 8; nt++) {
                    int col = nt * 8 + 2 * q;
                    float2 b = *reinterpret_cast<const float2*>(bb + col);
                    float2 o0 = *reinterpret_cast<const float2*>(stage + r * SR + col);
                    float2 o1 = *reinterpret_cast<const float2*>(stage + (r + 8) * SR + col);
                    o0.x += elu_f(C[mt][nt][0] + b.x); o0.y += elu_f(C[mt][nt][1] + b.y);
                    o1.x += elu_f(C[mt][nt][2] + b.x); o1.y += elu_f(C[mt][nt][3] + b.y);
                    *reinterpret_cast<float2*>(stage + r * SR + col) = o0;
                    *reinterpret_cast<float2*>(stage + (r + 8) * SR + col) = o1;
                }
            }
            __syncwarp();
        }

        // ---- regression head: pred = elu(h @ Wr1 + br1) @ Wr2 + br2 ----
        {
            float C[2][4][4];
            #pragma unroll
            for (int mt = 0; mt < 2; mt++)
                #pragma unroll
                for (int nt = 0; nt < 4; nt++)
                    #pragma unroll
                    for (int i = 0; i < 4; i++) C[mt][nt][i] = 0.0f;
            warp_gemm<8, 4>(C, stage, 0, S + OFF_WR1, lane);
            const float br2v = S[OFF_BR2];
            #pragma unroll
            for (int mt = 0; mt < 2; mt++) {
                float s0 = 0.0f, s1 = 0.0f;
                #pragma unroll
                for (int nt = 0; nt < 4; nt++) {
                    int col = nt * 8 + 2 * q;
                    float2 b = *reinterpret_cast<const float2*>(S + OFF_BR1 + col);
                    float2 w = *reinterpret_cast<const float2*>(S + OFF_WR2 + col);
                    s0 += elu_f(C[mt][nt][0] + b.x) * w.x + elu_f(C[mt][nt][1] + b.y) * w.y;
                    s1 += elu_f(C[mt][nt][2] + b.x) * w.x + elu_f(C[mt][nt][3] + b.y) * w.y;
                }
                s0 += __shfl_xor_sync(0xFFFFFFFFu, s0, 1);
                s0 += __shfl_xor_sync(0xFFFFFFFFu, s0, 2);
                s1 += __shfl_xor_sync(0xFFFFFFFFu, s1, 1);
                s1 += __shfl_xor_sync(0xFFFFFFFFu, s1, 2);
                if (q == 0) {
                    int r = row0 + mt * 16 + g;
                    if (r < B)     out[r]     = s0 + br2v;
                    if (r + 8 < B) out[r + 8] = s1 + br2v;
                }
            }
        }

        // ---- classification head: logits = elu(h @ Wc1 + bc1) @ Wc2 + bc2 ----
        {
            float C[2][4][4];
            #pragma unroll
            for (int mt = 0; mt < 2; mt++)
                #pragma unroll
                for (int nt = 0; nt < 4; nt++)
                    #pragma unroll
                    for (int i = 0; i < 4; i++) C[mt][nt][i] = 0.0f;
            warp_gemm<8, 4>(C, stage, 0, S + OFF_WC1, lane);
            float4 bc2v = *reinterpret_cast<const float4*>(S + OFF_BC2);
            #pragma unroll
            for (int mt = 0; mt < 2; mt++) {
                float4 v0 = make_float4(0.f, 0.f, 0.f, 0.f);
                float4 v1 = make_float4(0.f, 0.f, 0.f, 0.f);
                #pragma unroll
                for (int nt = 0; nt < 4; nt++) {
                    int col = nt * 8 + 2 * q;
                    float2 b = *reinterpret_cast<const float2*>(S + OFF_BC1 + col);
                    float e0 = elu_f(C[mt][nt][0] + b.x), e1 = elu_f(C[mt][nt][1] + b.y);
                    float e2 = elu_f(C[mt][nt][2] + b.x), e3 = elu_f(C[mt][nt][3] + b.y);
                    float4 w0 = *reinterpret_cast<const float4*>(S + OFF_WC2 + col * 4);
                    float4 w1 = *reinterpret_cast<const float4*>(S + OFF_WC2 + (col + 1) * 4);
                    v0.x += e0 * w0.x + e1 * w1.x; v0.y += e0 * w0.y + e1 * w1.y;
                    v0.z += e0 * w0.z + e1 * w1.z; v0.w += e0 * w0.w + e1 * w1.w;
                    v1.x += e2 * w0.x + e3 * w1.x; v1.y += e2 * w0.y + e3 * w1.y;
                    v1.z += e2 * w0.z + e3 * w1.z; v1.w += e2 * w0.w + e3 * w1.w;
                }
                #pragma unroll
                for (int d = 1; d <= 2; d <<= 1) {
                    v0.x += __shfl_xor_sync(0xFFFFFFFFu, v0.x, d);
                    v0.y += __shfl_xor_sync(0xFFFFFFFFu, v0.y, d);
                    v0.z += __shfl_xor_sync(0xFFFFFFFFu, v0.z, d);
                    v0.w += __shfl_xor_sync(0xFFFFFFFFu, v0.w, d);
                    v1.x += __shfl_xor_sync(0xFFFFFFFFu, v1.x, d);
                    v1.y += __shfl_xor_sync(0xFFFFFFFFu, v1.y, d);
                    v1.z += __shfl_xor_sync(0xFFFFFFFFu, v1.z, d);
                    v1.w += __shfl_xor_sync(0xFFFFFFFFu, v1.w, d);
                }
                if (q == 0) {
                    int r = row0 + mt * 16 + g;
                    if (r < B) {
                        float4 o = make_float4(v0.x + bc2v.x, v0.y + bc2v.y, v0.z + bc2v.z, v0.w + bc2v.w);
                        *reinterpret_cast<float4*>(out + B + 4LL * r) = o;
                    }
                    if (r + 8 < B) {
                        float4 o = make_float4(v1.x + bc2v.x, v1.y + bc2v.y, v1.z + bc2v.z, v1.w + bc2v.w);
                        *reinterpret_cast<float4*>(out + B + 4LL * (r + 8)) = o;
                    }
                }
            }
        }
        __syncwarp();
    }
}

extern "C" void kernel_launch(void* const* d_in, const int* in_sizes, int n_in,
                              void* d_out, int out_size) {
    const float* x    = (const float*)d_in[0];
    const float* Wsym = (const float*)d_in[1];
    const float* bsym = (const float*)d_in[2];
    const float* Win  = (const float*)d_in[3];
    const float* bin_ = (const float*)d_in[4];
    const float* W1   = (const float*)d_in[5];
    const float* b1   = (const float*)d_in[6];
    const float* W2   = (const float*)d_in[7];
    const float* b2   = (const float*)d_in[8];
    const float* W3   = (const float*)d_in[9];
    const float* b3   = (const float*)d_in[10];
    const float* Wr1  = (const float*)d_in[11];
    const float* br1  = (const float*)d_in[12];
    const float* Wr2  = (const float*)d_in[13];
    const float* br2  = (const float*)d_in[14];
    const float* Wc1  = (const float*)d_in[15];
    const float* bc1  = (const float*)d_in[16];
    const float* Wc2  = (const float*)d_in[17];
    const float* bc2  = (const float*)d_in[18];
    float* out = (float*)d_out;

    int B = in_sizes[0] / 10;

    cudaFuncSetAttribute(robustsym_mma_kernel,
                         cudaFuncAttributeMaxDynamicSharedMemorySize, SMEM_BYTES);

    robustsym_mma_kernel<<<GRID, THREADS, SMEM_BYTES>>>(
        x, Wsym, bsym, Win, bin_, W1, b1, W2, b2, W3, b3,
        Wr1, br1, Wr2, br2, Wc1, bc1, Wc2, bc2, out, B);
}

// round 6
// speedup vs baseline: 2.6421x; 1.6343x over previous
#include <cuda_runtime.h>

#define THREADS 384
#define WARPS 12
#define GRID 148
#define SR 72               // staging row stride (floats); (SR/2)%32==4 -> float2 accesses conflict-free
#define TILE_ROWS 32

// ---- smem layout ----
// Weight region (u32 units, viewing smem as unsigned*): per GEMM [hi(sz) | lo(sz)],
// entry ((kt*TN+nt)*32+lane)*2 + r  packs bf16x2 for B-frag reg r of mma.m16n8k16.
#define OFF_WSYM 0            // TK=1 TN=4 : sz 256  -> occupies 512
#define OFF_WIN  512          // TK=3 TN=8 : sz 1536 -> 3072
#define OFF_W1   3584         // TK=4 TN=8 : sz 2048 -> 4096 each, x3
#define OFF_WR1  15872        // TK=4 TN=4 : sz 1024 -> 2048
#define OFF_WC1  17920        // 2048
// bias region (float units)
#define OFF_BSYM 19968
#define OFF_BIN  20000
#define OFF_B1   20064        // 64*3
#define OFF_BR1  20256
#define OFF_WR2  20288
#define OFF_BC1  20320
#define OFF_WC2  20352        // 32x4
#define OFF_BC2  20480
#define OFF_BR2  20484
#define OFF_STAGE 20488
#define STAGE_PER_WARP (TILE_ROWS * SR)    // 2304
#define SMEM_FLOATS (OFF_STAGE + WARPS * STAGE_PER_WARP)
#define SMEM_BYTES (SMEM_FLOATS * 4)

__device__ __forceinline__ float elu_f(float v) {
    if (v > 0.0f) return v;
    if (v < -0.03125f) return __expf(v) - 1.0f;
    return v * (1.0f + v * (0.5f + v * (0.16666667f + v * 0.041666668f)));
}

// mma.sync m16n8k16 bf16 with fp32 accumulate (in-place C)
__device__ __forceinline__ void mma_bf16(float* c, const unsigned* a, unsigned b0, unsigned b1) {
    asm volatile(
        "mma.sync.aligned.m16n8k16.row.col.f32.bf16.bf16.f32 "
        "{%0,%1,%2,%3},{%4,%5,%6,%7},{%8,%9},{%0,%1,%2,%3};\n"
        : "+f"(c[0]), "+f"(c[1]), "+f"(c[2]), "+f"(c[3])
        : "r"(a[0]), "r"(a[1]), "r"(a[2]), "r"(a[3]), "r"(b0), "r"(b1));
}

// Exact truncation split of a float2 into packed-bf16 hi and round-nearest packed-bf16 lo.
// hi = top 16 bits of each float (exact bf16, a = hi + lo exactly); lo then RN-rounded to bf16.
__device__ __forceinline__ void split_pair(float2 f, unsigned& hi, unsigned& lo) {
    unsigned bx = __float_as_uint(f.x), by = __float_as_uint(f.y);
    unsigned h;
    asm("prmt.b32 %0, %1, %2, 0x7632;" : "=r"(h) : "r"(bx), "r"(by));  // low16=hi(f.x), high16=hi(f.y)
    float lx = f.x - __uint_as_float(bx & 0xFFFF0000u);
    float ly = f.y - __uint_as_float(by & 0xFFFF0000u);
    unsigned l;
    asm("cvt.rn.bf16x2.f32 %0, %1, %2;" : "=r"(l) : "f"(ly), "f"(lx));  // low=lx, high=ly
    hi = h; lo = l;
}

// Stage W[K,N] (row-major) into permuted packed-bf16 hi/lo B-fragment layout, zero-padded.
__device__ void stage_weights_bf16(unsigned* dsthi, unsigned* dstlo, const float* __restrict__ src,
                                   int K, int N, int TK, int TN) {
    int total = TK * TN * 64;
    for (int i = threadIdx.x; i < total; i += THREADS) {
        int r    = i & 1;
        int lane = (i >> 1) & 31;
        int t    = i >> 6;
        int kt = t / TN, nt = t % TN;
        int q = lane & 3, g = lane >> 2;
        int k0 = kt * 16 + r * 8 + 2 * q;
        int n  = nt * 8 + g;
        float w0 = (k0     < K && n < N) ? src[k0 * N + n]       : 0.0f;
        float w1 = (k0 + 1 < K && n < N) ? src[(k0 + 1) * N + n] : 0.0f;
        unsigned h, l;
        split_pair(make_float2(w0, w1), h, l);
        dsthi[i] = h; dstlo[i] = l;
    }
}

__device__ __forceinline__ void cp_smem(float* dst, const float* __restrict__ src, int n) {
    for (int i = threadIdx.x; i < n; i += THREADS) dst[i] = src[i];
}

// Warp GEMM (3x bf16 split): C[2][TN][4] += stage[:, colbase : colbase+16*TK] @ W
template <int TK, int TN>
__device__ __forceinline__ void warp_gemm(float C[2][TN][4], const float* stage,
                                          int colbase, const unsigned* Whi, const unsigned* Wlo,
                                          int lane) {
    const int q = lane & 3, g = lane >> 2;
    #pragma unroll
    for (int kt = 0; kt < TK; kt++) {
        const int c = colbase + kt * 16 + 2 * q;
        unsigned ahi[2][4], alo[2][4];
        #pragma unroll
        for (int mt = 0; mt < 2; mt++) {
            const float* s0 = stage + (mt * 16 + g) * SR;
            const float* s1 = stage + (mt * 16 + 8 + g) * SR;
            split_pair(*(const float2*)(s0 + c),     ahi[mt][0], alo[mt][0]);
            split_pair(*(const float2*)(s1 + c),     ahi[mt][1], alo[mt][1]);
            split_pair(*(const float2*)(s0 + c + 8), ahi[mt][2], alo[mt][2]);
            split_pair(*(const float2*)(s1 + c + 8), ahi[mt][3], alo[mt][3]);
        }
        #pragma unroll
        for (int nt = 0; nt < TN; nt++) {
            uint2 bh = *(const uint2*)(Whi + ((kt * TN + nt) * 32 + lane) * 2);
            uint2 bl = *(const uint2*)(Wlo + ((kt * TN + nt) * 32 + lane) * 2);
            #pragma unroll
            for (int mt = 0; mt < 2; mt++) {
                mma_bf16(C[mt][nt], ahi[mt], bh.x, bh.y);   // hi*hi
                mma_bf16(C[mt][nt], alo[mt], bh.x, bh.y);   // lo*hi
                mma_bf16(C[mt][nt], ahi[mt], bl.x, bl.y);   // hi*lo
            }
        }
    }
}

__global__ void __launch_bounds__(THREADS, 1) robustsym_mma_kernel(
    const float* __restrict__ x,
    const float* __restrict__ gWsym, const float* __restrict__ gbsym,
    const float* __restrict__ gWin,  const float* __restrict__ gbin,
    const float* __restrict__ gW1,   const float* __restrict__ gb1,
    const float* __restrict__ gW2,   const float* __restrict__ gb2,
    const float* __restrict__ gW3,   const float* __restrict__ gb3,
    const float* __restrict__ gWr1,  const float* __restrict__ gbr1,
    const float* __restrict__ gWr2,  const float* __restrict__ gbr2,
    const float* __restrict__ gWc1,  const float* __restrict__ gbc1,
    const float* __restrict__ gWc2,  const float* __restrict__ gbc2,
    float* __restrict__ out, int B)
{
    extern __shared__ float S[];
    unsigned* U = reinterpret_cast<unsigned*>(S);

    // ---- one-time weight split+permute and bias staging ----
    stage_weights_bf16(U + OFF_WSYM, U + OFF_WSYM + 256,  gWsym, 10, 32, 1, 4);
    stage_weights_bf16(U + OFF_WIN,  U + OFF_WIN  + 1536, gWin,  42, 64, 3, 8);
    stage_weights_bf16(U + OFF_W1,           U + OFF_W1 + 2048,        gW1, 64, 64, 4, 8);
    stage_weights_bf16(U + OFF_W1 + 4096,    U + OFF_W1 + 6144,        gW2, 64, 64, 4, 8);
    stage_weights_bf16(U + OFF_W1 + 8192,    U + OFF_W1 + 10240,       gW3, 64, 64, 4, 8);
    stage_weights_bf16(U + OFF_WR1, U + OFF_WR1 + 1024, gWr1, 64, 32, 4, 4);
    stage_weights_bf16(U + OFF_WC1, U + OFF_WC1 + 1024, gWc1, 64, 32, 4, 4);
    cp_smem(S + OFF_BSYM, gbsym, 32);
    cp_smem(S + OFF_BIN,  gbin,  64);
    cp_smem(S + OFF_B1,        gb1, 64);
    cp_smem(S + OFF_B1 + 64,   gb2, 64);
    cp_smem(S + OFF_B1 + 128,  gb3, 64);
    cp_smem(S + OFF_BR1, gbr1, 32);
    cp_smem(S + OFF_WR2, gWr2, 32);
    cp_smem(S + OFF_BC1, gbc1, 32);
    cp_smem(S + OFF_WC2, gWc2, 128);
    cp_smem(S + OFF_BC2, gbc2, 4);
    if (threadIdx.x == 0) S[OFF_BR2] = gbr2[0];
    __syncthreads();

    const int wid  = threadIdx.x >> 5;
    const int lane = threadIdx.x & 31;
    const int q = lane & 3, g = lane >> 2;
    float* stage = S + OFF_STAGE + wid * STAGE_PER_WARP;

    const int ntiles = (B + TILE_ROWS - 1) / TILE_ROWS;
    const int gw = blockIdx.x * WARPS + wid;

    for (int tile = gw; tile < ntiles; tile += GRID * WARPS) {
        const int row0 = tile * TILE_ROWS;

        // ---- phase 0: per-lane row load + symbolic features -> staging (float2 stores) ----
        {
            int row = row0 + lane;
            int rq = row < B ? row : B - 1;
            float xr[10];
            #pragma unroll
            for (int i = 0; i < 10; i++) xr[i] = __ldg(x + (long long)rq * 10 + i);

            const float am = xr[0], bod = xr[1], dox = xr[2], ph = xr[4], nit = xr[7];
            float p_ph  = ph  < 6.5f   ? (6.5f   - ph ) * (1.0f/6.5f)  : (ph  > 8.5f ? (ph  - 8.5f) * (1.0f/8.5f) : 0.0f);
            float p_am  = am  < 0.001f ? (0.001f - am ) * 1000.0f      : (am  > 0.5f ? (am  - 0.5f) * 2.0f        : 0.0f);
            float p_bod = bod < 0.001f ? (0.001f - bod) * 1000.0f      : (bod > 5.0f ? (bod - 5.0f) * 0.2f        : 0.0f);
            float p_do  = dox < 6.0f   ? (6.0f   - dox) * (1.0f/6.0f)  : 0.0f;
            float p_nit = nit < 0.001f ? (0.001f - nit) * 1000.0f      : (nit > 10.0f ? (nit - 10.0f) * 0.1f      : 0.0f);
            float s_bact = am * 0.79999998f + bod * 0.099999998f - dox * 0.026666667f;
            float s_chem = ph * 0.088235293f + nit * 0.050000000f;
            float s_org  = bod * 0.13333333f - dox * 0.050000000f + am * 0.53333332f;
            float s_agr  = nit * 0.19999999980000002f;
            float psum   = p_ph + p_am + p_bod + p_do + p_nit;
            float resil  = 1.0f / (1.0f + psum + 1e-8f);

            float2* sr = (float2*)(stage + lane * SR);
            sr[0] = make_float2(xr[0], xr[1]);
            sr[1] = make_float2(xr[2], xr[3]);
            sr[2] = make_float2(xr[4], xr[5]);
            sr[3] = make_float2(xr[6], xr[7]);
            sr[4] = make_float2(xr[8], xr[9]);
            sr[5] = make_float2(p_ph, p_am);
            sr[6] = make_float2(p_bod, p_do);
            sr[7] = make_float2(p_nit, s_bact);
            sr[8] = make_float2(s_chem, s_org);
            sr[9] = make_float2(s_agr, resil);
            sr[10] = make_float2(0.f, 0.f);   // cols 20..25 pad (sym GEMM K 10->16)
            sr[11] = make_float2(0.f, 0.f);
            sr[12] = make_float2(0.f, 0.f);
            sr[21] = make_float2(0.f, 0.f);   // cols 42..47 pad (input GEMM K 42->48)
            sr[22] = make_float2(0.f, 0.f);
            sr[23] = make_float2(0.f, 0.f);
        }
        __syncwarp();

        // ---- GEMM A: sym_enc = elu(sym @ W_sym + b_sym)  [K=16p, N=32] -> cols 10..41 ----
        {
            float C[2][4][4];
            #pragma unroll
            for (int mt = 0; mt < 2; mt++)
                #pragma unroll
                for (int nt = 0; nt < 4; nt++)
                    #pragma unroll
                    for (int i = 0; i < 4; i++) C[mt][nt][i] = 0.0f;
            warp_gemm<1, 4>(C, stage, 10, U + OFF_WSYM, U + OFF_WSYM + 256, lane);
            __syncwarp();
            #pragma unroll
            for (int mt = 0; mt < 2; mt++) {
                int r = mt * 16 + g;
                #pragma unroll
                for (int nt = 0; nt < 4; nt++) {
                    int col = nt * 8 + 2 * q;
                    float2 b = *reinterpret_cast<const float2*>(S + OFF_BSYM + col);
                    *reinterpret_cast<float2*>(stage + r * SR + 10 + col) =
                        make_float2(elu_f(C[mt][nt][0] + b.x), elu_f(C[mt][nt][1] + b.y));
                    *reinterpret_cast<float2*>(stage + (r + 8) * SR + 10 + col) =
                        make_float2(elu_f(C[mt][nt][2] + b.x), elu_f(C[mt][nt][3] + b.y));
                }
            }
        }
        __syncwarp();

        // ---- GEMM B: h = elu([x|sym_enc] @ W_in + b_in)  [K=48p, N=64] -> cols 0..63 ----
        {
            float C[2][8][4];
            #pragma unroll
            for (int mt = 0; mt < 2; mt++)
                #pragma unroll
                for (int nt = 0; nt < 8; nt++)
                    #pragma unroll
                    for (int i = 0; i < 4; i++) C[mt][nt][i] = 0.0f;
            warp_gemm<3, 8>(C, stage, 0, U + OFF_WIN, U + OFF_WIN + 1536, lane);
            __syncwarp();
            #pragma unroll
            for (int mt = 0; mt < 2; mt++) {
                int r = mt * 16 + g;
                #pragma unroll
                for (int nt = 0; nt < 8; nt++) {
                    int col = nt * 8 + 2 * q;
                    float2 b = *reinterpret_cast<const float2*>(S + OFF_BIN + col);
                    *reinterpret_cast<float2*>(stage + r * SR + col) =
                        make_float2(elu_f(C[mt][nt][0] + b.x), elu_f(C[mt][nt][1] + b.y));
                    *reinterpret_cast<float2*>(stage + (r + 8) * SR + col) =
                        make_float2(elu_f(C[mt][nt][2] + b.x), elu_f(C[mt][nt][3] + b.y));
                }
            }
        }
        __syncwarp();

        // ---- residual blocks: h = h + elu(h @ W + b)  x3 ----
        #pragma unroll 1
        for (int l = 0; l < 3; l++) {
            float C[2][8][4];
            #pragma unroll
            for (int mt = 0; mt < 2; mt++)
                #pragma unroll
                for (int nt = 0; nt < 8; nt++)
                    #pragma unroll
                    for (int i = 0; i < 4; i++) C[mt][nt][i] = 0.0f;
            warp_gemm<4, 8>(C, stage, 0, U + OFF_W1 + l * 4096, U + OFF_W1 + l * 4096 + 2048, lane);
            __syncwarp();
            const float* bb = S + OFF_B1 + l * 64;
            #pragma unroll
            for (int mt = 0; mt < 2; mt++) {
                int r = mt * 16 + g;
                #pragma unroll
                for (int nt = 0; nt < 8; nt++) {
                    int col = nt * 8 + 2 * q;
                    float2 b = *reinterpret_cast<const float2*>(bb + col);
                    float2 o0 = *reinterpret_cast<const float2*>(stage + r * SR + col);
                    float2 o1 = *reinterpret_cast<const float2*>(stage + (r + 8) * SR + col);
                    o0.x += elu_f(C[mt][nt][0] + b.x); o0.y += elu_f(C[mt][nt][1] + b.y);
                    o1.x += elu_f(C[mt][nt][2] + b.x); o1.y += elu_f(C[mt][nt][3] + b.y);
                    *reinterpret_cast<float2*>(stage + r * SR + col) = o0;
                    *reinterpret_cast<float2*>(stage + (r + 8) * SR + col) = o1;
                }
            }
            __syncwarp();
        }

        // ---- regression head: pred = elu(h @ Wr1 + br1) @ Wr2 + br2 ----
        {
            float C[2][4][4];
            #pragma unroll
            for (int mt = 0; mt < 2; mt++)
                #pragma unroll
                for (int nt = 0; nt < 4; nt++)
                    #pragma unroll
                    for (int i = 0; i < 4; i++) C[mt][nt][i] = 0.0f;
            warp_gemm<4, 4>(C, stage, 0, U + OFF_WR1, U + OFF_WR1 + 1024, lane);
            const float br2v = S[OFF_BR2];
            #pragma unroll
            for (int mt = 0; mt < 2; mt++) {
                float s0 = 0.0f, s1 = 0.0f;
                #pragma unroll
                for (int nt = 0; nt < 4; nt++) {
                    int col = nt * 8 + 2 * q;
                    float2 b = *reinterpret_cast<const float2*>(S + OFF_BR1 + col);
                    float2 w = *reinterpret_cast<const float2*>(S + OFF_WR2 + col);
                    s0 += elu_f(C[mt][nt][0] + b.x) * w.x + elu_f(C[mt][nt][1] + b.y) * w.y;
                    s1 += elu_f(C[mt][nt][2] + b.x) * w.x + elu_f(C[mt][nt][3] + b.y) * w.y;
                }
                s0 += __shfl_xor_sync(0xFFFFFFFFu, s0, 1);
                s0 += __shfl_xor_sync(0xFFFFFFFFu, s0, 2);
                s1 += __shfl_xor_sync(0xFFFFFFFFu, s1, 1);
                s1 += __shfl_xor_sync(0xFFFFFFFFu, s1, 2);
                if (q == 0) {
                    int r = row0 + mt * 16 + g;
                    if (r < B)     out[r]     = s0 + br2v;
                    if (r + 8 < B) out[r + 8] = s1 + br2v;
                }
            }
        }

        // ---- classification head: logits = elu(h @ Wc1 + bc1) @ Wc2 + bc2 ----
        {
            float C[2][4][4];
            #pragma unroll
            for (int mt = 0; mt < 2; mt++)
                #pragma unroll
                for (int nt = 0; nt < 4; nt++)
                    #pragma unroll
                    for (int i = 0; i < 4; i++) C[mt][nt][i] = 0.0f;
            warp_gemm<4, 4>(C, stage, 0, U + OFF_WC1, U + OFF_WC1 + 1024, lane);
            float4 bc2v = *reinterpret_cast<const float4*>(S + OFF_BC2);
            #pragma unroll
            for (int mt = 0; mt < 2; mt++) {
                float4 v0 = make_float4(0.f, 0.f, 0.f, 0.f);
                float4 v1 = make_float4(0.f, 0.f, 0.f, 0.f);
                #pragma unroll
                for (int nt = 0; nt < 4; nt++) {
                    int col = nt * 8 + 2 * q;
                    float2 b = *reinterpret_cast<const float2*>(S + OFF_BC1 + col);
                    float e0 = elu_f(C[mt][nt][0] + b.x), e1 = elu_f(C[mt][nt][1] + b.y);
                    float e2 = elu_f(C[mt][nt][2] + b.x), e3 = elu_f(C[mt][nt][3] + b.y);
                    float4 w0 = *reinterpret_cast<const float4*>(S + OFF_WC2 + col * 4);
                    float4 w1 = *reinterpret_cast<const float4*>(S + OFF_WC2 + (col + 1) * 4);
                    v0.x += e0 * w0.x + e1 * w1.x; v0.y += e0 * w0.y + e1 * w1.y;
                    v0.z += e0 * w0.z + e1 * w1.z; v0.w += e0 * w0.w + e1 * w1.w;
                    v1.x += e2 * w0.x + e3 * w1.x; v1.y += e2 * w0.y + e3 * w1.y;
                    v1.z += e2 * w0.z + e3 * w1.z; v1.w += e2 * w0.w + e3 * w1.w;
                }
                #pragma unroll
                for (int d = 1; d <= 2; d <<= 1) {
                    v0.x += __shfl_xor_sync(0xFFFFFFFFu, v0.x, d);
                    v0.y += __shfl_xor_sync(0xFFFFFFFFu, v0.y, d);
                    v0.z += __shfl_xor_sync(0xFFFFFFFFu, v0.z, d);
                    v0.w += __shfl_xor_sync(0xFFFFFFFFu, v0.w, d);
                    v1.x += __shfl_xor_sync(0xFFFFFFFFu, v1.x, d);
                    v1.y += __shfl_xor_sync(0xFFFFFFFFu, v1.y, d);
                    v1.z += __shfl_xor_sync(0xFFFFFFFFu, v1.z, d);
                    v1.w += __shfl_xor_sync(0xFFFFFFFFu, v1.w, d);
                }
                if (q == 0) {
                    int r = row0 + mt * 16 + g;
                    if (r < B) {
                        float4 o = make_float4(v0.x + bc2v.x, v0.y + bc2v.y, v0.z + bc2v.z, v0.w + bc2v.w);
                        *reinterpret_cast<float4*>(out + B + 4LL * r) = o;
                    }
                    if (r + 8 < B) {
                        float4 o = make_float4(v1.x + bc2v.x, v1.y + bc2v.y, v1.z + bc2v.z, v1.w + bc2v.w);
                        *reinterpret_cast<float4*>(out + B + 4LL * (r + 8)) = o;
                    }
                }
            }
        }
        __syncwarp();
    }
}

extern "C" void kernel_launch(void* const* d_in, const int* in_sizes, int n_in,
                              void* d_out, int out_size) {
    const float* x    = (const float*)d_in[0];
    const float* Wsym = (const float*)d_in[1];
    const float* bsym = (const float*)d_in[2];
    const float* Win  = (const float*)d_in[3];
    const float* bin_ = (const float*)d_in[4];
    const float* W1   = (const float*)d_in[5];
    const float* b1   = (const float*)d_in[6];
    const float* W2   = (const float*)d_in[7];
    const float* b2   = (const float*)d_in[8];
    const float* W3   = (const float*)d_in[9];
    const float* b3   = (const float*)d_in[10];
    const float* Wr1  = (const float*)d_in[11];
    const float* br1  = (const float*)d_in[12];
    const float* Wr2  = (const float*)d_in[13];
    const float* br2  = (const float*)d_in[14];
    const float* Wc1  = (const float*)d_in[15];
    const float* bc1  = (const float*)d_in[16];
    const float* Wc2  = (const float*)d_in[17];
    const float* bc2  = (const float*)d_in[18];
    float* out = (float*)d_out;

    int B = in_sizes[0] / 10;

    cudaFuncSetAttribute(robustsym_mma_kernel,
                         cudaFuncAttributeMaxDynamicSharedMemorySize, SMEM_BYTES);

    robustsym_mma_kernel<<<GRID, THREADS, SMEM_BYTES>>>(
        x, Wsym, bsym, Win, bin_, W1, b1, W2, b2, W3, b3,
        Wr1, br1, Wr2, br2, Wc1, bc1, Wc2, bc2, out, B);
}

// round 7
// speedup vs baseline: 6.0295x; 2.2821x over previous
#include <cuda_runtime.h>

#define THREADS 512
#define WARPS 16
#define GRID 148
#define TILE_ROWS 32
#define SSRU 18             // staging row stride in uint2 (conflict-free frag reads, 2-way write)

// ---- smem layout ----
// Weight region (u32 units): per GEMM [hi(sz) | lo(sz)], entry ((kt*TN+nt)*32+lane)*2+r
// packs bf16x2 for B-frag of mma.m16n8k16.
#define OFF_WSYM 0            // TK=1 TN=4 : sz 256  -> 512
#define OFF_WIN  512          // TK=3 TN=8 : sz 1536 -> 3072  (rows permuted: [sym32|x10|pad6])
#define OFF_W1   3584         // TK=4 TN=8 : sz 2048 -> 4096 each, x3
#define OFF_WHD  15872        // heads combined Wr1(nt0..3)+Wc1(nt4..7): TK=4 TN=8 -> 4096
// bias region (float units)
#define OFF_BSYM 19968
#define OFF_BIN  20000
#define OFF_B1   20064        // 64*3
#define OFF_BR1  20256
#define OFF_WR2  20288
#define OFF_BC1  20320
#define OFF_WC2  20352        // 32x4
#define OFF_BC2  20480
#define OFF_BR2  20484
#define OFF_STAGE 20488       // float offset; per-warp 32 rows * 18 uint2
#define STAGE_U2_PER_WARP (TILE_ROWS * SSRU)
#define SMEM_FLOATS (OFF_STAGE + WARPS * STAGE_U2_PER_WARP * 2)
#define SMEM_BYTES (SMEM_FLOATS * 4)

// branchless ELU: abs error ~1e-7 for tiny negative v (aggregate-rel harmless)
__device__ __forceinline__ float elu_f(float v) {
    float e = __expf(v) - 1.0f;
    return v > 0.0f ? v : e;
}

__device__ __forceinline__ void mma_bf16(float* c, const unsigned* a, unsigned b0, unsigned b1) {
    asm volatile(
        "mma.sync.aligned.m16n8k16.row.col.f32.bf16.bf16.f32 "
        "{%0,%1,%2,%3},{%4,%5,%6,%7},{%8,%9},{%0,%1,%2,%3};\n"
        : "+f"(c[0]), "+f"(c[1]), "+f"(c[2]), "+f"(c[3])
        : "r"(a[0]), "r"(a[1]), "r"(a[2]), "r"(a[3]), "r"(b0), "r"(b1));
}

// Exact truncation split: hi = top-16 bits (bf16x2: low16 from f.x), lo = RN-bf16x2 of residual.
__device__ __forceinline__ void split_pair(float2 f, unsigned& hi, unsigned& lo) {
    unsigned bx = __float_as_uint(f.x), by = __float_as_uint(f.y);
    unsigned h;
    asm("prmt.b32 %0, %1, %2, 0x7632;" : "=r"(h) : "r"(bx), "r"(by));
    float lx = f.x - __uint_as_float(bx & 0xFFFF0000u);
    float ly = f.y - __uint_as_float(by & 0xFFFF0000u);
    unsigned l;
    asm("cvt.rn.bf16x2.f32 %0, %1, %2;" : "=r"(l) : "f"(ly), "f"(lx));
    hi = h; lo = l;
}

// 3x-split MMA step: C += A * B with hh + lh + hl terms.
__device__ __forceinline__ void mma3(float* c, const unsigned* ahi, const unsigned* alo,
                                     const unsigned* Whi, const unsigned* Wlo, int idx) {
    uint2 bh = *(const uint2*)(Whi + idx);
    uint2 bl = *(const uint2*)(Wlo + idx);
    mma_bf16(c, ahi, bh.x, bh.y);
    mma_bf16(c, alo, bh.x, bh.y);
    mma_bf16(c, ahi, bl.x, bl.y);
}

// Pack A-fragment (one kt, one mt) from two ELU'd C tiles (C layout == A layout).
__device__ __forceinline__ void pack_frag(const float* c0, const float* c1,
                                          unsigned* ahi, unsigned* alo) {
    split_pair(make_float2(c0[0], c0[1]), ahi[0], alo[0]);
    split_pair(make_float2(c0[2], c0[3]), ahi[1], alo[1]);
    split_pair(make_float2(c1[0], c1[1]), ahi[2], alo[2]);
    split_pair(make_float2(c1[2], c1[3]), ahi[3], alo[3]);
}

// Stage W[K,N] row-major -> permuted packed-bf16 hi/lo B-frag layout, zero-padded.
// perm=1: W_in row remap (dst feature order [sym_enc(32)|x(10)|pad(6)]).
__device__ void stage_w(unsigned* dsthi, unsigned* dstlo, const float* __restrict__ src,
                        int K, int N, int TK, int TN_dst, int srcT, int nt_off, int perm) {
    int total = TK * srcT * 64;
    for (int i = threadIdx.x; i < total; i += THREADS) {
        int r = i & 1, lane = (i >> 1) & 31, t = i >> 6;
        int kt = t / srcT, ntl = t % srcT;
        int q = lane & 3, g = lane >> 2;
        int k0 = kt * 16 + r * 8 + 2 * q;
        int n = ntl * 8 + g;
        float w0 = 0.0f, w1 = 0.0f;
        if (n < N) {
            int k = perm ? ((k0 < 32) ? k0 + 10 : (k0 < 42 ? k0 - 32 : -1))
                         : (k0 < K ? k0 : -1);
            if (k >= 0) w0 = src[k * N + n];
            int k1 = k0 + 1;
            k = perm ? ((k1 < 32) ? k1 + 10 : (k1 < 42 ? k1 - 32 : -1))
                     : (k1 < K ? k1 : -1);
            if (k >= 0) w1 = src[k * N + n];
        }
        unsigned h, l;
        split_pair(make_float2(w0, w1), h, l);
        int di = ((kt * TN_dst + nt_off + ntl) * 32 + lane) * 2 + r;
        dsthi[di] = h; dstlo[di] = l;
    }
}

__device__ __forceinline__ void cp_smem(float* dst, const float* __restrict__ src, int n) {
    for (int i = threadIdx.x; i < n; i += THREADS) dst[i] = src[i];
}

__global__ void __launch_bounds__(THREADS, 1) robustsym_mma_kernel(
    const float* __restrict__ x,
    const float* __restrict__ gWsym, const float* __restrict__ gbsym,
    const float* __restrict__ gWin,  const float* __restrict__ gbin,
    const float* __restrict__ gW1,   const float* __restrict__ gb1,
    const float* __restrict__ gW2,   const float* __restrict__ gb2,
    const float* __restrict__ gW3,   const float* __restrict__ gb3,
    const float* __restrict__ gWr1,  const float* __restrict__ gbr1,
    const float* __restrict__ gWr2,  const float* __restrict__ gbr2,
    const float* __restrict__ gWc1,  const float* __restrict__ gbc1,
    const float* __restrict__ gWc2,  const float* __restrict__ gbc2,
    float* __restrict__ out, int B)
{
    extern __shared__ float S[];
    unsigned* U = reinterpret_cast<unsigned*>(S);

    // ---- one-time weight split+permute and bias staging ----
    stage_w(U + OFF_WSYM, U + OFF_WSYM + 256,  gWsym, 10, 32, 1, 4, 4, 0, 0);
    stage_w(U + OFF_WIN,  U + OFF_WIN  + 1536, gWin,  42, 64, 3, 8, 8, 0, 1);
    stage_w(U + OFF_W1,        U + OFF_W1 + 2048,  gW1, 64, 64, 4, 8, 8, 0, 0);
    stage_w(U + OFF_W1 + 4096, U + OFF_W1 + 6144,  gW2, 64, 64, 4, 8, 8, 0, 0);
    stage_w(U + OFF_W1 + 8192, U + OFF_W1 + 10240, gW3, 64, 64, 4, 8, 8, 0, 0);
    stage_w(U + OFF_WHD, U + OFF_WHD + 2048, gWr1, 64, 32, 4, 8, 4, 0, 0);
    stage_w(U + OFF_WHD, U + OFF_WHD + 2048, gWc1, 64, 32, 4, 8, 4, 4, 0);
    cp_smem(S + OFF_BSYM, gbsym, 32);
    cp_smem(S + OFF_BIN,  gbin,  64);
    cp_smem(S + OFF_B1,       gb1, 64);
    cp_smem(S + OFF_B1 + 64,  gb2, 64);
    cp_smem(S + OFF_B1 + 128, gb3, 64);
    cp_smem(S + OFF_BR1, gbr1, 32);
    cp_smem(S + OFF_WR2, gWr2, 32);
    cp_smem(S + OFF_BC1, gbc1, 32);
    cp_smem(S + OFF_WC2, gWc2, 128);
    cp_smem(S + OFF_BC2, gbc2, 4);
    if (threadIdx.x == 0) S[OFF_BR2] = gbr2[0];
    __syncthreads();

    const int wid  = threadIdx.x >> 5;
    const int lane = threadIdx.x & 31;
    const int q = lane & 3, g = lane >> 2;
    uint2* U2w = reinterpret_cast<uint2*>(S + OFF_STAGE) + wid * STAGE_U2_PER_WARP;

    const int ntiles = (B + TILE_ROWS - 1) / TILE_ROWS;
    const int gw = blockIdx.x * WARPS + wid;

    for (int tile = gw; tile < ntiles; tile += GRID * WARPS) {
        const int row0 = tile * TILE_ROWS;

        // ---- phase 0: per-lane features, pre-split into staging (uint2 = hi,lo) ----
        {
            int row = row0 + lane;
            int rq = row < B ? row : B - 1;
            float xr[10];
            #pragma unroll
            for (int i = 0; i < 10; i++) xr[i] = __ldg(x + (long long)rq * 10 + i);

            const float am = xr[0], bod = xr[1], dox = xr[2], ph = xr[4], nit = xr[7];
            float p_ph  = ph  < 6.5f   ? (6.5f   - ph ) * (1.0f/6.5f)  : (ph  > 8.5f ? (ph  - 8.5f) * (1.0f/8.5f) : 0.0f);
            float p_am  = am  < 0.001f ? (0.001f - am ) * 1000.0f      : (am  > 0.5f ? (am  - 0.5f) * 2.0f        : 0.0f);
            float p_bod = bod < 0.001f ? (0.001f - bod) * 1000.0f      : (bod > 5.0f ? (bod - 5.0f) * 0.2f        : 0.0f);
            float p_do  = dox < 6.0f   ? (6.0f   - dox) * (1.0f/6.0f)  : 0.0f;
            float p_nit = nit < 0.001f ? (0.001f - nit) * 1000.0f      : (nit > 10.0f ? (nit - 10.0f) * 0.1f      : 0.0f);
            float s_bact = am * 0.79999998f + bod * 0.099999998f - dox * 0.026666667f;
            float s_chem = ph * 0.088235293f + nit * 0.050000000f;
            float s_org  = bod * 0.13333333f - dox * 0.050000000f + am * 0.53333332f;
            float s_agr  = nit * 0.19999999980000002f;
            float psum   = p_ph + p_am + p_bod + p_do + p_nit;
            float resil  = 1.0f / (1.0f + psum + 1e-8f);

            uint2* sw = U2w + lane * SSRU;
            unsigned h, l;
            split_pair(make_float2(p_ph, p_am),   h, l); sw[0]  = make_uint2(h, l);
            split_pair(make_float2(p_bod, p_do),  h, l); sw[1]  = make_uint2(h, l);
            split_pair(make_float2(p_nit, s_bact),h, l); sw[2]  = make_uint2(h, l);
            split_pair(make_float2(s_chem, s_org),h, l); sw[3]  = make_uint2(h, l);
            split_pair(make_float2(s_agr, resil), h, l); sw[4]  = make_uint2(h, l);
            sw[5] = make_uint2(0, 0); sw[6] = make_uint2(0, 0); sw[7] = make_uint2(0, 0);
            split_pair(make_float2(xr[0], xr[1]), h, l); sw[8]  = make_uint2(h, l);
            split_pair(make_float2(xr[2], xr[3]), h, l); sw[9]  = make_uint2(h, l);
            split_pair(make_float2(xr[4], xr[5]), h, l); sw[10] = make_uint2(h, l);
            split_pair(make_float2(xr[6], xr[7]), h, l); sw[11] = make_uint2(h, l);
            split_pair(make_float2(xr[8], xr[9]), h, l); sw[12] = make_uint2(h, l);
            sw[13] = make_uint2(0, 0); sw[14] = make_uint2(0, 0); sw[15] = make_uint2(0, 0);
        }
        __syncwarp();

        // ---- two independent 16-row halves ----
        #pragma unroll 1
        for (int mt = 0; mt < 2; mt++) {
            const int r0 = mt * 16 + g, r1 = r0 + 8;

            // ---- GEMM A: sym_enc = elu(sym @ W_sym + b_sym)  [16 x 16 -> 32] ----
            float Ca[4][4];
            #pragma unroll
            for (int nt = 0; nt < 4; nt++)
                #pragma unroll
                for (int i = 0; i < 4; i++) Ca[nt][i] = 0.0f;
            {
                unsigned ahi[4], alo[4];
                uint2 v0 = U2w[r0 * SSRU + q],     v1 = U2w[r1 * SSRU + q];
                uint2 v2 = U2w[r0 * SSRU + 4 + q], v3 = U2w[r1 * SSRU + 4 + q];
                ahi[0] = v0.x; alo[0] = v0.y; ahi[1] = v1.x; alo[1] = v1.y;
                ahi[2] = v2.x; alo[2] = v2.y; ahi[3] = v3.x; alo[3] = v3.y;
                #pragma unroll
                for (int nt = 0; nt < 4; nt++)
                    mma3(Ca[nt], ahi, alo, U + OFF_WSYM, U + OFF_WSYM + 256,
                         (nt * 32 + lane) * 2);
            }
            #pragma unroll
            for (int nt = 0; nt < 4; nt++) {
                float2 b = *reinterpret_cast<const float2*>(S + OFF_BSYM + nt * 8 + 2 * q);
                Ca[nt][0] = elu_f(Ca[nt][0] + b.x); Ca[nt][1] = elu_f(Ca[nt][1] + b.y);
                Ca[nt][2] = elu_f(Ca[nt][2] + b.x); Ca[nt][3] = elu_f(Ca[nt][3] + b.y);
            }

            // pack sym_enc into A-frags for GEMM B kt=0,1 (register-to-register)
            unsigned bhA[2][4], blA[2][4];
            pack_frag(Ca[0], Ca[1], bhA[0], blA[0]);
            pack_frag(Ca[2], Ca[3], bhA[1], blA[1]);

            // ---- GEMM B: h = elu([sym_enc|x] @ Win_perm + b_in)  [16 x 48 -> 64] ----
            float h[8][4];
            #pragma unroll
            for (int nt = 0; nt < 8; nt++)
                #pragma unroll
                for (int i = 0; i < 4; i++) h[nt][i] = 0.0f;
            #pragma unroll
            for (int kt = 0; kt < 2; kt++)
                #pragma unroll
                for (int nt = 0; nt < 8; nt++)
                    mma3(h[nt], bhA[kt], blA[kt], U + OFF_WIN, U + OFF_WIN + 1536,
                         ((kt * 8 + nt) * 32 + lane) * 2);
            {
                unsigned ahi[4], alo[4];
                uint2 v0 = U2w[r0 * SSRU + 8 + q],  v1 = U2w[r1 * SSRU + 8 + q];
                uint2 v2 = U2w[r0 * SSRU + 12 + q], v3 = U2w[r1 * SSRU + 12 + q];
                ahi[0] = v0.x; alo[0] = v0.y; ahi[1] = v1.x; alo[1] = v1.y;
                ahi[2] = v2.x; alo[2] = v2.y; ahi[3] = v3.x; alo[3] = v3.y;
                #pragma unroll
                for (int nt = 0; nt < 8; nt++)
                    mma3(h[nt], ahi, alo, U + OFF_WIN, U + OFF_WIN + 1536,
                         ((2 * 8 + nt) * 32 + lane) * 2);
            }
            #pragma unroll
            for (int nt = 0; nt < 8; nt++) {
                float2 b = *reinterpret_cast<const float2*>(S + OFF_BIN + nt * 8 + 2 * q);
                h[nt][0] = elu_f(h[nt][0] + b.x); h[nt][1] = elu_f(h[nt][1] + b.y);
                h[nt][2] = elu_f(h[nt][2] + b.x); h[nt][3] = elu_f(h[nt][3] + b.y);
            }

            // ---- residual blocks: h = h + elu(h @ W + b)  x3, fully in registers ----
            #pragma unroll 1
            for (int l = 0; l < 3; l++) {
                const unsigned* Whi = U + OFF_W1 + l * 4096;
                const unsigned* Wlo = Whi + 2048;
                float C[8][4];
                #pragma unroll
                for (int nt = 0; nt < 8; nt++)
                    #pragma unroll
                    for (int i = 0; i < 4; i++) C[nt][i] = 0.0f;
                #pragma unroll
                for (int kt = 0; kt < 4; kt++) {
                    unsigned ahi[4], alo[4];
                    pack_frag(h[2 * kt], h[2 * kt + 1], ahi, alo);
                    #pragma unroll
                    for (int nt = 0; nt < 8; nt++)
                        mma3(C[nt], ahi, alo, Whi, Wlo, ((kt * 8 + nt) * 32 + lane) * 2);
                }
                const float* bb = S + OFF_B1 + l * 64;
                #pragma unroll
                for (int nt = 0; nt < 8; nt++) {
                    float2 b = *reinterpret_cast<const float2*>(bb + nt * 8 + 2 * q);
                    h[nt][0] += elu_f(C[nt][0] + b.x); h[nt][1] += elu_f(C[nt][1] + b.y);
                    h[nt][2] += elu_f(C[nt][2] + b.x); h[nt][3] += elu_f(C[nt][3] + b.y);
                }
            }

            // ---- heads (combined TN=8: nt0..3 = Wr1, nt4..7 = Wc1) ----
            float C[8][4];
            #pragma unroll
            for (int nt = 0; nt < 8; nt++)
                #pragma unroll
                for (int i = 0; i < 4; i++) C[nt][i] = 0.0f;
            #pragma unroll
            for (int kt = 0; kt < 4; kt++) {
                unsigned ahi[4], alo[4];
                pack_frag(h[2 * kt], h[2 * kt + 1], ahi, alo);
                #pragma unroll
                for (int nt = 0; nt < 8; nt++)
                    mma3(C[nt], ahi, alo, U + OFF_WHD, U + OFF_WHD + 2048,
                         ((kt * 8 + nt) * 32 + lane) * 2);
            }

            // regression: pred = elu(C[0..3] + br1) @ Wr2 + br2
            {
                const float br2v = S[OFF_BR2];
                float s0 = 0.0f, s1 = 0.0f;
                #pragma unroll
                for (int nt = 0; nt < 4; nt++) {
                    int col = nt * 8 + 2 * q;
                    float2 b = *reinterpret_cast<const float2*>(S + OFF_BR1 + col);
                    float2 w = *reinterpret_cast<const float2*>(S + OFF_WR2 + col);
                    s0 += elu_f(C[nt][0] + b.x) * w.x + elu_f(C[nt][1] + b.y) * w.y;
                    s1 += elu_f(C[nt][2] + b.x) * w.x + elu_f(C[nt][3] + b.y) * w.y;
                }
                s0 += __shfl_xor_sync(0xFFFFFFFFu, s0, 1);
                s0 += __shfl_xor_sync(0xFFFFFFFFu, s0, 2);
                s1 += __shfl_xor_sync(0xFFFFFFFFu, s1, 1);
                s1 += __shfl_xor_sync(0xFFFFFFFFu, s1, 2);
                if (q == 0) {
                    int r = row0 + mt * 16 + g;
                    if (r < B)     out[r]     = s0 + br2v;
                    if (r + 8 < B) out[r + 8] = s1 + br2v;
                }
            }

            // classification: logits = elu(C[4..7] + bc1) @ Wc2 + bc2
            {
                float4 bc2v = *reinterpret_cast<const float4*>(S + OFF_BC2);
                float4 v0 = make_float4(0.f, 0.f, 0.f, 0.f);
                float4 v1 = make_float4(0.f, 0.f, 0.f, 0.f);
                #pragma unroll
                for (int ntl = 0; ntl < 4; ntl++) {
                    const float* Cc = C[4 + ntl];
                    int col = ntl * 8 + 2 * q;
                    float2 b = *reinterpret_cast<const float2*>(S + OFF_BC1 + col);
                    float e0 = elu_f(Cc[0] + b.x), e1 = elu_f(Cc[1] + b.y);
                    float e2 = elu_f(Cc[2] + b.x), e3 = elu_f(Cc[3] + b.y);
                    float4 w0 = *reinterpret_cast<const float4*>(S + OFF_WC2 + col * 4);
                    float4 w1 = *reinterpret_cast<const float4*>(S + OFF_WC2 + (col + 1) * 4);
                    v0.x += e0 * w0.x + e1 * w1.x; v0.y += e0 * w0.y + e1 * w1.y;
                    v0.z += e0 * w0.z + e1 * w1.z; v0.w += e0 * w0.w + e1 * w1.w;
                    v1.x += e2 * w0.x + e3 * w1.x; v1.y += e2 * w0.y + e3 * w1.y;
                    v1.z += e2 * w0.z + e3 * w1.z; v1.w += e2 * w0.w + e3 * w1.w;
                }
                #pragma unroll
                for (int d = 1; d <= 2; d <<= 1) {
                    v0.x += __shfl_xor_sync(0xFFFFFFFFu, v0.x, d);
                    v0.y += __shfl_xor_sync(0xFFFFFFFFu, v0.y, d);
                    v0.z += __shfl_xor_sync(0xFFFFFFFFu, v0.z, d);
                    v0.w += __shfl_xor_sync(0xFFFFFFFFu, v0.w, d);
                    v1.x += __shfl_xor_sync(0xFFFFFFFFu, v1.x, d);
                    v1.y += __shfl_xor_sync(0xFFFFFFFFu, v1.y, d);
                    v1.z += __shfl_xor_sync(0xFFFFFFFFu, v1.z, d);
                    v1.w += __shfl_xor_sync(0xFFFFFFFFu, v1.w, d);
                }
                if (q == 0) {
                    int r = row0 + mt * 16 + g;
                    if (r < B) {
                        float4 o = make_float4(v0.x + bc2v.x, v0.y + bc2v.y,
                                               v0.z + bc2v.z, v0.w + bc2v.w);
                        *reinterpret_cast<float4*>(out + B + 4LL * r) = o;
                    }
                    if (r + 8 < B) {
                        float4 o = make_float4(v1.x + bc2v.x, v1.y + bc2v.y,
                                               v1.z + bc2v.z, v1.w + bc2v.w);
                        *reinterpret_cast<float4*>(out + B + 4LL * (r + 8)) = o;
                    }
                }
            }
        }
        __syncwarp();
    }
}

extern "C" void kernel_launch(void* const* d_in, const int* in_sizes, int n_in,
                              void* d_out, int out_size) {
    const float* x    = (const float*)d_in[0];
    const float* Wsym = (const float*)d_in[1];
    const float* bsym = (const float*)d_in[2];
    const float* Win  = (const float*)d_in[3];
    const float* bin_ = (const float*)d_in[4];
    const float* W1   = (const float*)d_in[5];
    const float* b1   = (const float*)d_in[6];
    const float* W2   = (const float*)d_in[7];
    const float* b2   = (const float*)d_in[8];
    const float* W3   = (const float*)d_in[9];
    const float* b3   = (const float*)d_in[10];
    const float* Wr1  = (const float*)d_in[11];
    const float* br1  = (const float*)d_in[12];
    const float* Wr2  = (const float*)d_in[13];
    const float* br2  = (const float*)d_in[14];
    const float* Wc1  = (const float*)d_in[15];
    const float* bc1  = (const float*)d_in[16];
    const float* Wc2  = (const float*)d_in[17];
    const float* bc2  = (const float*)d_in[18];
    float* out = (float*)d_out;

    int B = in_sizes[0] / 10;

    cudaFuncSetAttribute(robustsym_mma_kernel,
                         cudaFuncAttributeMaxDynamicSharedMemorySize, SMEM_BYTES);

    robustsym_mma_kernel<<<GRID, THREADS, SMEM_BYTES>>>(
        x, Wsym, bsym, Win, bin_, W1, b1, W2, b2, W3, b3,
        Wr1, br1, Wr2, br2, Wc1, bc1, Wc2, bc2, out, B);
}